// round 10
// baseline (speedup 1.0000x reference)
#include <cuda_runtime.h>
#include <cuda_fp16.h>
#include <math.h>
#include <stdint.h>

#define HH   256
#define HW   65536
#define WHF  129
#define DIM  128
#define HID  512
#define NB   4
#define NLAYERS 4

typedef __half f16;

// ---------------- scratch (device globals) ----------------
__device__ float  g_h[(size_t)NB * DIM * HW];          // residual [b][c][p] fp32
__device__ float  g_z[(size_t)NB * DIM * HW];          // fft input fp32
__device__ float2 g_xf[(size_t)NB * DIM * WHF * 256];
__device__ float2 g_filt[(size_t)DIM * WHF * 256];
__device__ f16    g_h16[(size_t)NB * DIM * HW];        // fp16 activations
__device__ f16    g_y16[(size_t)NB * HID * HW];
__device__ f16    g_z16[(size_t)NB * DIM * HW];
__device__ f16    g_w1h[(size_t)NLAYERS * HID * DIM], g_w1l[(size_t)NLAYERS * HID * DIM];
__device__ f16    g_w2h[(size_t)NLAYERS * DIM * HID], g_w2l[(size_t)NLAYERS * DIM * HID];
__device__ f16    g_oxh[(size_t)NLAYERS * DIM * DIM], g_oxl[(size_t)NLAYERS * DIM * DIM];

// ---------------- helpers ----------------
__device__ __forceinline__ int drev4(int x) {
    return ((x & 3) << 6) | (((x >> 2) & 3) << 4) | (((x >> 4) & 3) << 2) | ((x >> 6) & 3);
}
__device__ __forceinline__ float2 cadd(float2 a, float2 b){ return make_float2(a.x+b.x, a.y+b.y); }
__device__ __forceinline__ float2 csub(float2 a, float2 b){ return make_float2(a.x-b.x, a.y-b.y); }
__device__ __forceinline__ float2 cmul(float2 a, float2 b){
    return make_float2(a.x*b.x - a.y*b.y, a.x*b.y + a.y*b.x);
}
__device__ __forceinline__ uint32_t smem_u32(const void* p) {
    uint32_t a;
    asm("{ .reg .u64 t; cvta.to.shared.u64 t, %1; cvt.u32.u64 %0, t; }" : "=r"(a) : "l"(p));
    return a;
}
__device__ __forceinline__ uint32_t pack_f16x2(float a, float b) {
    return ((uint32_t)__half_as_ushort(__float2half_rn(b)) << 16)
         |  (uint32_t)__half_as_ushort(__float2half_rn(a));
}

// ================= mma.sync primitives =================
__device__ __forceinline__ void ldsm4(uint32_t* r, uint32_t addr) {
    asm volatile("ldmatrix.sync.aligned.m8n8.x4.shared.b16 {%0,%1,%2,%3}, [%4];"
                 : "=r"(r[0]), "=r"(r[1]), "=r"(r[2]), "=r"(r[3]) : "r"(addr));
}
__device__ __forceinline__ void ldsm4t(uint32_t* r, uint32_t addr) {
    asm volatile("ldmatrix.sync.aligned.m8n8.x4.trans.shared.b16 {%0,%1,%2,%3}, [%4];"
                 : "=r"(r[0]), "=r"(r[1]), "=r"(r[2]), "=r"(r[3]) : "r"(addr));
}
__device__ __forceinline__ void mma16816(float* c, const uint32_t* a, const uint32_t* b) {
    asm volatile(
        "mma.sync.aligned.m16n8k16.row.col.f32.f16.f16.f32 "
        "{%0,%1,%2,%3}, {%4,%5,%6,%7}, {%8,%9}, {%0,%1,%2,%3};"
        : "+f"(c[0]), "+f"(c[1]), "+f"(c[2]), "+f"(c[3])
        : "r"(a[0]), "r"(a[1]), "r"(a[2]), "r"(a[3]), "r"(b[0]), "r"(b[1]));
}
__device__ __forceinline__ void cp16(uint32_t dst, const void* src) {
    asm volatile("cp.async.cg.shared.global [%0], [%1], 16;" :: "r"(dst), "l"(src));
}

// ================= fp16 2-pass pipelined tensor-core GEMM =================
// 512 threads, tile 128m x 256n, warp grid 4x4. A = weights fp16 hi/lo, B = act fp16.
// C = (Ah+Al)*B + bias (+epi).  EPI: 0 -> fp32 Cf; 1 -> silu -> f16 Ch; 2 -> +res(Cf) -> Cf + f16 Ch
template <int K, int M, int EPI>
__global__ void __launch_bounds__(512, 1)
gemm_mma(const f16* __restrict__ Ah, const f16* __restrict__ Al,
         const f16* __restrict__ Bm,
         const float* __restrict__ bias,
         float* __restrict__ Cf, f16* __restrict__ Ch)
{
    constexpr int NC = K / 32;
    constexpr int STAGE = 32768;                     // [Ah 8K][Al 8K][B 16K]
    extern __shared__ uint8_t smem[];                // 3 stages
    uint32_t sbase = smem_u32(smem);

    int tid  = threadIdx.x;
    int lane = tid & 31;
    int warp = tid >> 5;
    int wm = warp >> 2, wn = warp & 3;

    const f16* Ahp = Ah + (size_t)blockIdx.y * 128 * K;
    const f16* Alp = Al + (size_t)blockIdx.y * 128 * K;
    const f16* Bp  = Bm + (size_t)blockIdx.z * K * HW + blockIdx.x * 256;

    const f16* gp[4];
    uint32_t   off[4];
    {
        int tile = tid >> 5, line = tid & 31;
        int am  = ((tile >> 1) << 4) + (line & 15);
        int agg = ((tile & 1) << 1) + (line >> 4);
        size_t aoff = (size_t)am * K + agg * 8;
        gp[0] = Ahp + aoff;  gp[1] = Alp + aoff;
        off[0] = tile * 512 + line * 16;
        off[1] = off[0] + 8192;
        int bk  = line & 15;
        int bgn = (tile & 15) * 2 + (line >> 4);     // n8 index 0..31
        gp[2] = Bp + (size_t)bk * HW + bgn * 8;        // k16 = 0
        gp[3] = Bp + (size_t)(bk + 16) * HW + bgn * 8; // k16 = 1
        off[2] = 16384 + tile * 512 + line * 16;
        off[3] = 16384 + (tile + 16) * 512 + line * 16;
    }

    auto issue = [&](int c) {
        uint32_t sst = sbase + (c % 3) * STAGE;
        cp16(sst + off[0], gp[0]);  gp[0] += 32;
        cp16(sst + off[1], gp[1]);  gp[1] += 32;
        cp16(sst + off[2], gp[2]);  gp[2] += (size_t)32 * HW;
        cp16(sst + off[3], gp[3]);  gp[3] += (size_t)32 * HW;
        asm volatile("cp.async.commit_group;" ::: "memory");
    };

    float acc[2][8][4] = {};

    issue(0);
    if (NC > 1) issue(1);

    for (int c = 0; c < NC; c++) {
        if (c + 1 < NC) {
            asm volatile("cp.async.wait_group 1;" ::: "memory");
        } else {
            asm volatile("cp.async.wait_group 0;" ::: "memory");
        }
        __syncthreads();
        uint32_t st = sbase + (c % 3) * STAGE;
#pragma unroll
        for (int kb = 0; kb < 2; kb++) {
            uint32_t ah[2][4], al[2][4];
#pragma unroll
            for (int i = 0; i < 2; i++) {
                uint32_t ad = st + ((((wm * 2 + i) * 2) + kb) << 9) + lane * 16;
                ldsm4(ah[i], ad);
                ldsm4(al[i], ad + 8192);
            }
#pragma unroll
            for (int r = 0; r < 4; r++) {
                uint32_t bh[4];
                uint32_t bd = st + 16384 + ((kb * 16 + wn * 4 + r) << 9) + lane * 16;
                ldsm4t(bh, bd);
#pragma unroll
                for (int i = 0; i < 2; i++)
#pragma unroll
                    for (int hh = 0; hh < 2; hh++) {
                        float* a_ = acc[i][r * 2 + hh];
                        mma16816(a_, ah[i], &bh[hh * 2]);
                        mma16816(a_, al[i], &bh[hh * 2]);
                    }
            }
        }
        __syncthreads();
        if (c + 2 < NC) issue(c + 2);
    }

    int g = lane >> 2;
    int mb0   = blockIdx.y * 128 + wm * 32;
    int nbase = blockIdx.x * 256 + wn * 64 + (lane & 3) * 2;
    size_t batch = (size_t)blockIdx.z * M * HW;
#pragma unroll
    for (int i = 0; i < 2; i++) {
        int r0 = mb0 + i * 16 + g;
        float bi0 = bias[r0], bi1 = bias[r0 + 8];
        size_t o0 = batch + (size_t)r0 * HW + nbase;
        size_t o1 = o0 + (size_t)8 * HW;
#pragma unroll
        for (int j = 0; j < 8; j++) {
            float v0 = acc[i][j][0] + bi0, v1 = acc[i][j][1] + bi0;
            float v2 = acc[i][j][2] + bi1, v3 = acc[i][j][3] + bi1;
            if (EPI == 1) {
                v0 = v0 / (1.f + __expf(-v0)); v1 = v1 / (1.f + __expf(-v1));
                v2 = v2 / (1.f + __expf(-v2)); v3 = v3 / (1.f + __expf(-v3));
            }
            if (EPI == 2) {
                float2 r0f = *(float2*)(Cf + o0 + j * 8);
                float2 r1f = *(float2*)(Cf + o1 + j * 8);
                v0 += r0f.x; v1 += r0f.y; v2 += r1f.x; v3 += r1f.y;
            }
            if (EPI == 0 || EPI == 2) {
                *(float2*)(Cf + o0 + j * 8) = make_float2(v0, v1);
                *(float2*)(Cf + o1 + j * 8) = make_float2(v2, v3);
            }
            if (EPI == 1 || EPI == 2) {
                *(uint32_t*)(Ch + o0 + j * 8) = pack_f16x2(v0, v1);
                *(uint32_t*)(Ch + o1 + j * 8) = pack_f16x2(v2, v3);
            }
        }
    }
}

// ---------------- weight split (fp16 hi/lo) ----------------
__global__ void wsplit(const float* __restrict__ w, f16* __restrict__ wh,
                       f16* __restrict__ wl, int n)
{
    int i = blockIdx.x * 256 + threadIdx.x;
    if (i >= n) return;
    float v = w[i];
    f16 h = __float2half_rn(v);
    wh[i] = h;
    wl[i] = __float2half_rn(v - __half2float(h));
}

// ---------------- radix-4 FFT building blocks (R9, verified) ----------------
#define TW_INIT256()                                                     \
    do { { float s_, c_;                                                 \
        sincospif(-(float)threadIdx.x / 128.0f, &s_, &c_);               \
        tw[threadIdx.x] = make_float2(c_, s_); } } while (0)

#define FFT4_DIF(dmat)                                                   \
    for (int s_ = 0; s_ < 4; s_++) {                                     \
        __syncthreads();                                                 \
        int q_  = 64 >> (2 * s_);                                        \
        int ts_ = 1 << (2 * s_);                                         \
        for (int u_ = threadIdx.x; u_ < 1024; u_ += 256) {               \
            int r_ = u_ >> 6, w_ = u_ & 63;                              \
            int j_ = w_ & (q_ - 1);                                      \
            int b_ = (w_ >> (6 - 2 * s_)) << (8 - 2 * s_);               \
            float2 a_  = dmat[r_][b_ + j_];                              \
            float2 bb_ = dmat[r_][b_ + j_ + q_];                         \
            float2 c_  = dmat[r_][b_ + j_ + 2 * q_];                     \
            float2 dd_ = dmat[r_][b_ + j_ + 3 * q_];                     \
            float2 t0 = cadd(a_, c_),  t1 = csub(a_, c_);                \
            float2 t2 = cadd(bb_, dd_), t3 = csub(bb_, dd_);             \
            float2 t3i = make_float2(t3.y, -t3.x);                       \
            int e_ = j_ * ts_;                                           \
            dmat[r_][b_ + j_]          = cadd(t0, t2);                   \
            dmat[r_][b_ + j_ + q_]     = cmul(cadd(t1, t3i), tw[e_]);    \
            dmat[r_][b_ + j_ + 2*q_]   = cmul(csub(t0, t2), tw[2*e_]);   \
            dmat[r_][b_ + j_ + 3*q_]   = cmul(csub(t1, t3i), tw[3*e_]);  \
        }                                                                \
    }                                                                    \
    __syncthreads();

#define FFT4_DIT_INV(dmat)                                               \
    for (int s_ = 0; s_ < 4; s_++) {                                     \
        __syncthreads();                                                 \
        int q_  = 1 << (2 * s_);                                         \
        int ts_ = 64 >> (2 * s_);                                        \
        for (int u_ = threadIdx.x; u_ < 1024; u_ += 256) {               \
            int r_ = u_ >> 6, w_ = u_ & 63;                              \
            int j_ = w_ & (q_ - 1);                                      \
            int b_ = (w_ >> (2 * s_)) << (2 * s_ + 2);                   \
            int e_ = j_ * ts_;                                           \
            float2 w1 = tw[e_];     w1.y = -w1.y;                        \
            float2 w2 = tw[2*e_];   w2.y = -w2.y;                        \
            float2 w3 = tw[3*e_];   w3.y = -w3.y;                        \
            float2 a_  = dmat[r_][b_ + j_];                              \
            float2 bb_ = cmul(dmat[r_][b_ + j_ + q_], w1);               \
            float2 c_  = cmul(dmat[r_][b_ + j_ + 2 * q_], w2);           \
            float2 dd_ = cmul(dmat[r_][b_ + j_ + 3 * q_], w3);           \
            float2 t0 = cadd(a_, c_),  t1 = csub(a_, c_);                \
            float2 t2 = cadd(bb_, dd_), t3 = csub(bb_, dd_);             \
            float2 t3i = make_float2(-t3.y, t3.x);                       \
            dmat[r_][b_ + j_]        = cadd(t0, t2);                     \
            dmat[r_][b_ + j_ + q_]   = cadd(t1, t3i);                    \
            dmat[r_][b_ + j_ + 2*q_] = csub(t0, t2);                     \
            dmat[r_][b_ + j_ + 3*q_] = csub(t1, t3i);                    \
        }                                                                \
    }                                                                    \
    __syncthreads();

__global__ void fft_row_fwd(const float* __restrict__ z, float2* __restrict__ xf)
{
    __shared__ float2 d[16][256];
    __shared__ float2 tw[256];
    TW_INIT256();
    int img = blockIdx.x;
    int y0  = blockIdx.y * 16;
    const float* src = z + (size_t)img * HW + (size_t)y0 * 256;
    for (int idx = threadIdx.x; idx < 4096; idx += 256)
        d[idx >> 8][idx & 255] = make_float2(src[idx], 0.f);
    FFT4_DIF(d);
    float2* dst = xf + (size_t)img * (WHF * 256) + y0;
    for (int idx = threadIdx.x; idx < WHF * 16; idx += 256) {
        int kx = idx >> 4, ry = idx & 15;
        dst[(size_t)kx * 256 + ry] = d[ry][drev4(kx)];
    }
}

__global__ void fft_col(float2* __restrict__ xf, const float2* __restrict__ filt)
{
    __shared__ float2 d[16][256];
    __shared__ float2 tw[256];
    TW_INIT256();
    size_t l0 = (size_t)blockIdx.x * 16;
    float2* src = xf + l0 * 256;
    float2* df = &d[0][0];
    for (int idx = threadIdx.x; idx < 4096; idx += 256)
        df[idx] = src[idx];
    FFT4_DIF(d);
    for (int idx = threadIdx.x; idx < 4096; idx += 256) {
        int r = idx >> 8;
        size_t fl = ((l0 + r) % (size_t)(DIM * WHF)) * 256;
        float2 f = filt[fl + (idx & 255)];
        df[idx] = cmul(df[idx], f);
    }
    FFT4_DIT_INV(d);
    for (int idx = threadIdx.x; idx < 4096; idx += 256)
        src[idx] = df[idx];
}

__global__ void fft_row_inv(const float2* __restrict__ xf, f16* __restrict__ zh)
{
    __shared__ float2 d[16][256];
    __shared__ float2 tw[256];
    TW_INIT256();
    int img = blockIdx.x;
    int y0  = blockIdx.y * 16;
    const float2* src = xf + (size_t)img * (WHF * 256) + y0;
    for (int idx = threadIdx.x; idx < WHF * 16; idx += 256) {
        int kx = idx >> 4, ry = idx & 15;
        d[ry][drev4(kx)] = src[(size_t)kx * 256 + ry];
    }
    __syncthreads();
    for (int q = threadIdx.x; q < 16 * 127; q += 256) {
        int r = q / 127;
        int k = 129 + (q % 127);
        float2 v = d[r][drev4(256 - k)];
        d[r][drev4(k)] = make_float2(v.x, -v.y);
    }
    FFT4_DIT_INV(d);
    size_t o = (size_t)img * HW + (size_t)y0 * 256;
    for (int idx = threadIdx.x; idx < 2048; idx += 256) {
        float v0 = d[idx >> 7][(idx & 127) * 2].x;
        float v1 = d[idx >> 7][(idx & 127) * 2 + 1].x;
        *(uint32_t*)(zh + o + idx * 2) = pack_f16x2(v0, v1);
    }
}

// ---------------- enc / dec / filter ----------------
__global__ void enc_kernel(const float* __restrict__ x, const float* __restrict__ w,
                           const float* __restrict__ bias, const float* __restrict__ pos,
                           float* __restrict__ h, f16* __restrict__ hh)
{
    int idx = blockIdx.x * 256 + threadIdx.x;
    if (idx >= NB * DIM * HW / 2) return;
    int e = idx * 2;
    int p = e & (HW - 1);
    int o = (e >> 16) & (DIM - 1);
    int b = e >> 23;
    float x0 = x[(size_t)(b * 2 + 0) * HW + p];
    float x1 = x[(size_t)(b * 2 + 1) * HW + p];
    float x0b = x[(size_t)(b * 2 + 0) * HW + p + 1];
    float x1b = x[(size_t)(b * 2 + 1) * HW + p + 1];
    float w0 = w[o * 2], w1 = w[o * 2 + 1], bb = bias[o];
    float v0 = (w0 * x0 + w1 * x1 + bb) * 8.0f + pos[(size_t)o * HW + p];
    float v1 = (w0 * x0b + w1 * x1b + bb) * 8.0f + pos[(size_t)o * HW + p + 1];
    *(float2*)(h + e) = make_float2(v0, v1);
    *(uint32_t*)(hh + e) = pack_f16x2(v0, v1);
}

__global__ void dec_kernel(const float* __restrict__ h, const float* __restrict__ w,
                           const float* __restrict__ bias, float* __restrict__ out)
{
    int idx = blockIdx.x * 256 + threadIdx.x;
    if (idx >= NB * HW) return;
    int p = idx & (HW - 1);
    int b = idx >> 16;
    const float* hb = h + (size_t)b * DIM * HW + p;
    float a0 = 0.f, a1 = 0.f;
#pragma unroll 4
    for (int c = 0; c < DIM; c++) {
        float hv = hb[(size_t)c * HW];
        a0 += w[c] * hv;
        a1 += w[DIM + c] * hv;
    }
    out[(size_t)(b * 2 + 0) * HW + p] = (a0 + bias[0]) * 0.125f;
    out[(size_t)(b * 2 + 1) * HW + p] = (a1 + bias[1]) * 0.125f;
}

__global__ void prep_filt(const float* __restrict__ mags, const float* __restrict__ phases,
                          float2* __restrict__ filt)
{
    int idx = blockIdx.x * 256 + threadIdx.x;
    if (idx >= DIM * HH * WHF) return;
    int kx = idx % WHF;
    int ky = (idx / WHF) % HH;
    int c  = idx / (WHF * HH);
    int kyp = (ky <= 128) ? ky : (256 - ky);
    float2 o = make_float2(0.f, 0.f);
    if (kx * kx + kyp * kyp <= 16384) {
        float sig = 1.0f / (1.0f + __expf(-mags[idx]));
        float s, co;
        sincosf(phases[idx], &s, &co);
        float sc = sig * (1.0f / 65536.0f);
        o = make_float2(sc * co, sc * s);
    }
    filt[(size_t)c * (WHF * 256) + (size_t)kx * 256 + drev4(ky)] = o;
}

// ---------------- launch ----------------
extern "C" void kernel_launch(void* const* d_in, const int* in_sizes, int n_in,
                              void* d_out, int out_size)
{
    const float* x      = (const float*)d_in[0];
    const float* enc_w  = (const float*)d_in[1];
    const float* enc_b  = (const float*)d_in[2];
    const float* pos    = (const float*)d_in[3];
    const float* w1     = (const float*)d_in[4];
    const float* b1     = (const float*)d_in[5];
    const float* w2     = (const float*)d_in[6];
    const float* b2     = (const float*)d_in[7];
    const float* mags   = (const float*)d_in[8];
    const float* phases = (const float*)d_in[9];
    const float* oxw    = (const float*)d_in[10];
    const float* oxb    = (const float*)d_in[11];
    const float* dw     = (const float*)d_in[12];
    const float* db     = (const float*)d_in[13];
    float* out = (float*)d_out;

    float *h, *z;
    float2 *xf, *ft;
    f16 *hh, *yh, *zh, *w1h, *w1l, *w2h, *w2l, *oxh, *oxl;
    cudaGetSymbolAddress((void**)&h,   g_h);
    cudaGetSymbolAddress((void**)&z,   g_z);
    cudaGetSymbolAddress((void**)&xf,  g_xf);
    cudaGetSymbolAddress((void**)&ft,  g_filt);
    cudaGetSymbolAddress((void**)&hh,  g_h16);
    cudaGetSymbolAddress((void**)&yh,  g_y16);
    cudaGetSymbolAddress((void**)&zh,  g_z16);
    cudaGetSymbolAddress((void**)&w1h, g_w1h);
    cudaGetSymbolAddress((void**)&w1l, g_w1l);
    cudaGetSymbolAddress((void**)&w2h, g_w2h);
    cudaGetSymbolAddress((void**)&w2l, g_w2l);
    cudaGetSymbolAddress((void**)&oxh, g_oxh);
    cudaGetSymbolAddress((void**)&oxl, g_oxl);

    const int SMEM = 3 * 32768;                      // 96 KB
    static bool attr = false;
    if (!attr) {
        cudaFuncSetAttribute(gemm_mma<128, 512, 1>, cudaFuncAttributeMaxDynamicSharedMemorySize, SMEM);
        cudaFuncSetAttribute(gemm_mma<512, 128, 0>, cudaFuncAttributeMaxDynamicSharedMemorySize, SMEM);
        cudaFuncSetAttribute(gemm_mma<128, 128, 2>, cudaFuncAttributeMaxDynamicSharedMemorySize, SMEM);
        attr = true;
    }

    wsplit<<<(NLAYERS * HID * DIM + 255) / 256, 256>>>(w1, w1h, w1l, NLAYERS * HID * DIM);
    wsplit<<<(NLAYERS * DIM * HID + 255) / 256, 256>>>(w2, w2h, w2l, NLAYERS * DIM * HID);
    wsplit<<<(NLAYERS * DIM * DIM + 255) / 256, 256>>>(oxw, oxh, oxl, NLAYERS * DIM * DIM);

    enc_kernel<<<(NB * DIM * HW / 2 + 255) / 256, 256>>>(x, enc_w, enc_b, pos, h, hh);

    const size_t specL = (size_t)DIM * HH * WHF;
    for (int i = 0; i < NLAYERS; i++) {
        prep_filt<<<(int)((specL + 255) / 256), 256>>>(mags + i * specL, phases + i * specL, ft);

        gemm_mma<128, 512, 1><<<dim3(256, 4, NB), 512, SMEM>>>(
            w1h + (size_t)i * HID * DIM, w1l + (size_t)i * HID * DIM,
            hh, b1 + i * HID, nullptr, yh);
        gemm_mma<512, 128, 0><<<dim3(256, 1, NB), 512, SMEM>>>(
            w2h + (size_t)i * DIM * HID, w2l + (size_t)i * DIM * HID,
            yh, b2 + i * DIM, z, nullptr);

        fft_row_fwd<<<dim3(NB * DIM, 16), 256>>>(z, xf);
        fft_col<<<(NB * DIM * WHF) / 16, 256>>>(xf, ft);
        fft_row_inv<<<dim3(NB * DIM, 16), 256>>>(xf, zh);

        gemm_mma<128, 128, 2><<<dim3(256, 1, NB), 512, SMEM>>>(
            oxh + (size_t)i * DIM * DIM, oxl + (size_t)i * DIM * DIM,
            zh, oxb + i * DIM, h, hh);
    }

    dec_kernel<<<(NB * HW + 255) / 256, 256>>>(h, dw, db, out);
}

// round 11
// speedup vs baseline: 1.5703x; 1.5703x over previous
#include <cuda_runtime.h>
#include <cuda_fp16.h>
#include <math.h>
#include <stdint.h>

#define HH   256
#define HW   65536
#define WHF  129
#define DIM  128
#define HID  512
#define NB   4
#define NLAYERS 4

typedef __half f16;

// ---------------- scratch (device globals) ----------------
__device__ float  g_h[(size_t)NB * DIM * HW];          // residual [b][c][p] fp32
__device__ float  g_z[(size_t)NB * DIM * HW];          // fft input fp32
__device__ __align__(16) float2 g_xf[(size_t)NB * DIM * WHF * 256];
__device__ __align__(16) float2 g_filt[(size_t)DIM * WHF * 256];
__device__ f16    g_h16[(size_t)NB * DIM * HW];        // fp16 activations
__device__ f16    g_y16[(size_t)NB * HID * HW];
__device__ f16    g_z16[(size_t)NB * DIM * HW];
__device__ f16    g_w1h[(size_t)NLAYERS * HID * DIM], g_w1l[(size_t)NLAYERS * HID * DIM];
__device__ f16    g_w2h[(size_t)NLAYERS * DIM * HID], g_w2l[(size_t)NLAYERS * DIM * HID];
__device__ f16    g_oxh[(size_t)NLAYERS * DIM * DIM], g_oxl[(size_t)NLAYERS * DIM * DIM];

// ---------------- helpers ----------------
__device__ __forceinline__ int drev4(int x) {
    return ((x & 3) << 6) | (((x >> 2) & 3) << 4) | (((x >> 4) & 3) << 2) | ((x >> 6) & 3);
}
__device__ __forceinline__ float2 cadd(float2 a, float2 b){ return make_float2(a.x+b.x, a.y+b.y); }
__device__ __forceinline__ float2 csub(float2 a, float2 b){ return make_float2(a.x-b.x, a.y-b.y); }
__device__ __forceinline__ float2 cmul(float2 a, float2 b){
    return make_float2(a.x*b.x - a.y*b.y, a.x*b.y + a.y*b.x);
}
__device__ __forceinline__ uint32_t smem_u32(const void* p) {
    uint32_t a;
    asm("{ .reg .u64 t; cvta.to.shared.u64 t, %1; cvt.u32.u64 %0, t; }" : "=r"(a) : "l"(p));
    return a;
}
__device__ __forceinline__ uint32_t pack_f16x2(float a, float b) {
    return ((uint32_t)__half_as_ushort(__float2half_rn(b)) << 16)
         |  (uint32_t)__half_as_ushort(__float2half_rn(a));
}

// ================= mma.sync primitives =================
__device__ __forceinline__ void ldsm4(uint32_t* r, uint32_t addr) {
    asm volatile("ldmatrix.sync.aligned.m8n8.x4.shared.b16 {%0,%1,%2,%3}, [%4];"
                 : "=r"(r[0]), "=r"(r[1]), "=r"(r[2]), "=r"(r[3]) : "r"(addr));
}
__device__ __forceinline__ void ldsm4t(uint32_t* r, uint32_t addr) {
    asm volatile("ldmatrix.sync.aligned.m8n8.x4.trans.shared.b16 {%0,%1,%2,%3}, [%4];"
                 : "=r"(r[0]), "=r"(r[1]), "=r"(r[2]), "=r"(r[3]) : "r"(addr));
}
__device__ __forceinline__ void mma16816(float* c, const uint32_t* a, const uint32_t* b) {
    asm volatile(
        "mma.sync.aligned.m16n8k16.row.col.f32.f16.f16.f32 "
        "{%0,%1,%2,%3}, {%4,%5,%6,%7}, {%8,%9}, {%0,%1,%2,%3};"
        : "+f"(c[0]), "+f"(c[1]), "+f"(c[2]), "+f"(c[3])
        : "r"(a[0]), "r"(a[1]), "r"(a[2]), "r"(a[3]), "r"(b[0]), "r"(b[1]));
}
__device__ __forceinline__ void cp16(uint32_t dst, const void* src) {
    asm volatile("cp.async.cg.shared.global [%0], [%1], 16;" :: "r"(dst), "l"(src));
}

// ================= fp16 2-pass pipelined tensor-core GEMM =================
// 512 threads, tile 128m x 256n, warp grid 4x4. A = weights fp16 hi/lo, B = act fp16.
// C = (Ah+Al)*B + bias (+epi).  EPI: 0 -> fp32 Cf; 1 -> silu -> f16 Ch; 2 -> +res(Cf) -> Cf + f16 Ch
template <int K, int M, int EPI>
__global__ void __launch_bounds__(512, 1)
gemm_mma(const f16* __restrict__ Ah, const f16* __restrict__ Al,
         const f16* __restrict__ Bm,
         const float* __restrict__ bias,
         float* __restrict__ Cf, f16* __restrict__ Ch)
{
    constexpr int NC = K / 32;
    constexpr int STAGE = 32768;                     // [Ah 8K][Al 8K][B 16K]
    extern __shared__ uint8_t smem[];                // 3 stages
    uint32_t sbase = smem_u32(smem);

    int tid  = threadIdx.x;
    int lane = tid & 31;
    int warp = tid >> 5;
    int wm = warp >> 2, wn = warp & 3;

    const f16* Ahp = Ah + (size_t)blockIdx.y * 128 * K;
    const f16* Alp = Al + (size_t)blockIdx.y * 128 * K;
    const f16* Bp  = Bm + (size_t)blockIdx.z * K * HW + blockIdx.x * 256;

    const f16* gp[4];
    uint32_t   off[4];
    {
        int tile = tid >> 5, line = tid & 31;
        int am  = ((tile >> 1) << 4) + (line & 15);
        int agg = ((tile & 1) << 1) + (line >> 4);
        size_t aoff = (size_t)am * K + agg * 8;
        gp[0] = Ahp + aoff;  gp[1] = Alp + aoff;
        off[0] = tile * 512 + line * 16;
        off[1] = off[0] + 8192;
        int bk  = line & 15;
        int bgn = (tile & 15) * 2 + (line >> 4);     // n8 index 0..31
        gp[2] = Bp + (size_t)bk * HW + bgn * 8;        // k16 = 0
        gp[3] = Bp + (size_t)(bk + 16) * HW + bgn * 8; // k16 = 1
        off[2] = 16384 + tile * 512 + line * 16;
        off[3] = 16384 + (tile + 16) * 512 + line * 16;
    }

    auto issue = [&](int c) {
        uint32_t sst = sbase + (c % 3) * STAGE;
        cp16(sst + off[0], gp[0]);  gp[0] += 32;
        cp16(sst + off[1], gp[1]);  gp[1] += 32;
        cp16(sst + off[2], gp[2]);  gp[2] += (size_t)32 * HW;
        cp16(sst + off[3], gp[3]);  gp[3] += (size_t)32 * HW;
        asm volatile("cp.async.commit_group;" ::: "memory");
    };

    float acc[2][8][4] = {};

    issue(0);
    if (NC > 1) issue(1);

    for (int c = 0; c < NC; c++) {
        if (c + 1 < NC) {
            asm volatile("cp.async.wait_group 1;" ::: "memory");
        } else {
            asm volatile("cp.async.wait_group 0;" ::: "memory");
        }
        __syncthreads();
        uint32_t st = sbase + (c % 3) * STAGE;
#pragma unroll
        for (int kb = 0; kb < 2; kb++) {
            uint32_t ah[2][4], al[2][4];
#pragma unroll
            for (int i = 0; i < 2; i++) {
                uint32_t ad = st + ((((wm * 2 + i) * 2) + kb) << 9) + lane * 16;
                ldsm4(ah[i], ad);
                ldsm4(al[i], ad + 8192);
            }
#pragma unroll
            for (int r = 0; r < 4; r++) {
                uint32_t bh[4];
                uint32_t bd = st + 16384 + ((kb * 16 + wn * 4 + r) << 9) + lane * 16;
                ldsm4t(bh, bd);
#pragma unroll
                for (int i = 0; i < 2; i++)
#pragma unroll
                    for (int hh = 0; hh < 2; hh++) {
                        float* a_ = acc[i][r * 2 + hh];
                        mma16816(a_, ah[i], &bh[hh * 2]);
                        mma16816(a_, al[i], &bh[hh * 2]);
                    }
            }
        }
        __syncthreads();
        if (c + 2 < NC) issue(c + 2);
    }

    int g = lane >> 2;
    int mb0   = blockIdx.y * 128 + wm * 32;
    int nbase = blockIdx.x * 256 + wn * 64 + (lane & 3) * 2;
    size_t batch = (size_t)blockIdx.z * M * HW;
#pragma unroll
    for (int i = 0; i < 2; i++) {
        int r0 = mb0 + i * 16 + g;
        float bi0 = bias[r0], bi1 = bias[r0 + 8];
        size_t o0 = batch + (size_t)r0 * HW + nbase;
        size_t o1 = o0 + (size_t)8 * HW;
#pragma unroll
        for (int j = 0; j < 8; j++) {
            float v0 = acc[i][j][0] + bi0, v1 = acc[i][j][1] + bi0;
            float v2 = acc[i][j][2] + bi1, v3 = acc[i][j][3] + bi1;
            if (EPI == 1) {
                v0 = v0 / (1.f + __expf(-v0)); v1 = v1 / (1.f + __expf(-v1));
                v2 = v2 / (1.f + __expf(-v2)); v3 = v3 / (1.f + __expf(-v3));
            }
            if (EPI == 2) {
                float2 r0f = *(float2*)(Cf + o0 + j * 8);
                float2 r1f = *(float2*)(Cf + o1 + j * 8);
                v0 += r0f.x; v1 += r0f.y; v2 += r1f.x; v3 += r1f.y;
            }
            if (EPI == 0 || EPI == 2) {
                *(float2*)(Cf + o0 + j * 8) = make_float2(v0, v1);
                *(float2*)(Cf + o1 + j * 8) = make_float2(v2, v3);
            }
            if (EPI == 1 || EPI == 2) {
                *(uint32_t*)(Ch + o0 + j * 8) = pack_f16x2(v0, v1);
                *(uint32_t*)(Ch + o1 + j * 8) = pack_f16x2(v2, v3);
            }
        }
    }
}

// ---------------- weight split (fp16 hi/lo) ----------------
__global__ void wsplit(const float* __restrict__ w, f16* __restrict__ wh,
                       f16* __restrict__ wl, int n)
{
    int i = blockIdx.x * 256 + threadIdx.x;
    if (i >= n) return;
    float v = w[i];
    f16 h = __float2half_rn(v);
    wh[i] = h;
    wl[i] = __float2half_rn(v - __half2float(h));
}

// ---------------- radix-4 FFT building blocks ----------------
#define TW_INIT256()                                                     \
    do { { float s_, c_;                                                 \
        sincospif(-(float)threadIdx.x / 128.0f, &s_, &c_);               \
        tw[threadIdx.x] = make_float2(c_, s_); } } while (0)

#define FFT4_DIF(dmat)                                                   \
    for (int s_ = 0; s_ < 4; s_++) {                                     \
        __syncthreads();                                                 \
        int q_  = 64 >> (2 * s_);                                        \
        int ts_ = 1 << (2 * s_);                                         \
        for (int u_ = threadIdx.x; u_ < 1024; u_ += 256) {               \
            int r_ = u_ >> 6, w_ = u_ & 63;                              \
            int j_ = w_ & (q_ - 1);                                      \
            int b_ = (w_ >> (6 - 2 * s_)) << (8 - 2 * s_);               \
            float2 a_  = dmat[r_][b_ + j_];                              \
            float2 bb_ = dmat[r_][b_ + j_ + q_];                         \
            float2 c_  = dmat[r_][b_ + j_ + 2 * q_];                     \
            float2 dd_ = dmat[r_][b_ + j_ + 3 * q_];                     \
            float2 t0 = cadd(a_, c_),  t1 = csub(a_, c_);                \
            float2 t2 = cadd(bb_, dd_), t3 = csub(bb_, dd_);             \
            float2 t3i = make_float2(t3.y, -t3.x);                       \
            int e_ = j_ * ts_;                                           \
            dmat[r_][b_ + j_]          = cadd(t0, t2);                   \
            dmat[r_][b_ + j_ + q_]     = cmul(cadd(t1, t3i), tw[e_]);    \
            dmat[r_][b_ + j_ + 2*q_]   = cmul(csub(t0, t2), tw[2*e_]);   \
            dmat[r_][b_ + j_ + 3*q_]   = cmul(csub(t1, t3i), tw[3*e_]);  \
        }                                                                \
    }                                                                    \
    __syncthreads();

#define FFT4_DIT_INV(dmat)                                               \
    for (int s_ = 0; s_ < 4; s_++) {                                     \
        __syncthreads();                                                 \
        int q_  = 1 << (2 * s_);                                         \
        int ts_ = 64 >> (2 * s_);                                        \
        for (int u_ = threadIdx.x; u_ < 1024; u_ += 256) {               \
            int r_ = u_ >> 6, w_ = u_ & 63;                              \
            int j_ = w_ & (q_ - 1);                                      \
            int b_ = (w_ >> (2 * s_)) << (2 * s_ + 2);                   \
            int e_ = j_ * ts_;                                           \
            float2 w1 = tw[e_];     w1.y = -w1.y;                        \
            float2 w2 = tw[2*e_];   w2.y = -w2.y;                        \
            float2 w3 = tw[3*e_];   w3.y = -w3.y;                        \
            float2 a_  = dmat[r_][b_ + j_];                              \
            float2 bb_ = cmul(dmat[r_][b_ + j_ + q_], w1);               \
            float2 c_  = cmul(dmat[r_][b_ + j_ + 2 * q_], w2);           \
            float2 dd_ = cmul(dmat[r_][b_ + j_ + 3 * q_], w3);           \
            float2 t0 = cadd(a_, c_),  t1 = csub(a_, c_);                \
            float2 t2 = cadd(bb_, dd_), t3 = csub(bb_, dd_);             \
            float2 t3i = make_float2(-t3.y, t3.x);                       \
            dmat[r_][b_ + j_]        = cadd(t0, t2);                     \
            dmat[r_][b_ + j_ + q_]   = cadd(t1, t3i);                    \
            dmat[r_][b_ + j_ + 2*q_] = csub(t0, t2);                     \
            dmat[r_][b_ + j_ + 3*q_] = csub(t1, t3i);                    \
        }                                                                \
    }                                                                    \
    __syncthreads();

__global__ void fft_row_fwd(const float* __restrict__ z, float2* __restrict__ xf)
{
    __shared__ __align__(16) float2 d[16][256];
    __shared__ float2 tw[256];
    TW_INIT256();
    int img = blockIdx.x;
    int y0  = blockIdx.y * 16;
    const float* src = z + (size_t)img * HW + (size_t)y0 * 256;
    // vectorized 16B loads: 4 reals -> 4 complex
    for (int q = threadIdx.x; q < 1024; q += 256) {
        float4 v = ((const float4*)src)[q];
        float4* row = (float4*)&d[q >> 6][(q & 63) * 4];
        row[0] = make_float4(v.x, 0.f, v.y, 0.f);
        row[1] = make_float4(v.z, 0.f, v.w, 0.f);
    }
    FFT4_DIF(d);
    float2* dst = xf + (size_t)img * (WHF * 256) + y0;
    for (int idx = threadIdx.x; idx < WHF * 16; idx += 256) {
        int kx = idx >> 4, ry = idx & 15;
        dst[(size_t)kx * 256 + ry] = d[ry][drev4(kx)];
    }
}

__global__ void fft_col(float2* __restrict__ xf, const float2* __restrict__ filt)
{
    __shared__ __align__(16) float2 d[16][256];
    __shared__ float2 tw[256];
    TW_INIT256();
    size_t l0 = (size_t)blockIdx.x * 16;
    float2* src = xf + l0 * 256;
    float4* src4 = (float4*)src;
    float4* df4 = (float4*)&d[0][0];
    float2* df  = &d[0][0];
    for (int q = threadIdx.x; q < 2048; q += 256)
        df4[q] = src4[q];
    FFT4_DIF(d);
    for (int q = threadIdx.x; q < 2048; q += 256) {
        int r  = q >> 7;
        int c0 = (q & 127) * 2;
        size_t fl = ((l0 + r) % (size_t)(DIM * WHF)) * 256;
        float4 fv = *(const float4*)(&filt[fl + c0]);
        float2 v0 = df[r * 256 + c0], v1 = df[r * 256 + c0 + 1];
        df[r * 256 + c0]     = cmul(v0, make_float2(fv.x, fv.y));
        df[r * 256 + c0 + 1] = cmul(v1, make_float2(fv.z, fv.w));
    }
    FFT4_DIT_INV(d);
    for (int q = threadIdx.x; q < 2048; q += 256)
        src4[q] = df4[q];
}

__global__ void fft_row_inv(const float2* __restrict__ xf, f16* __restrict__ zh)
{
    __shared__ __align__(16) float2 d[16][256];
    __shared__ float2 tw[256];
    TW_INIT256();
    int img = blockIdx.x;
    int y0  = blockIdx.y * 16;
    const float2* src = xf + (size_t)img * (WHF * 256) + y0;
    for (int idx = threadIdx.x; idx < WHF * 16; idx += 256) {
        int kx = idx >> 4, ry = idx & 15;
        d[ry][drev4(kx)] = src[(size_t)kx * 256 + ry];
    }
    __syncthreads();
    for (int q = threadIdx.x; q < 16 * 127; q += 256) {
        int r = q / 127;
        int k = 129 + (q % 127);
        float2 v = d[r][drev4(256 - k)];
        d[r][drev4(k)] = make_float2(v.x, -v.y);
    }
    FFT4_DIT_INV(d);
    size_t o = (size_t)img * HW + (size_t)y0 * 256;
    for (int idx = threadIdx.x; idx < 2048; idx += 256) {
        float v0 = d[idx >> 7][(idx & 127) * 2].x;
        float v1 = d[idx >> 7][(idx & 127) * 2 + 1].x;
        *(uint32_t*)(zh + o + idx * 2) = pack_f16x2(v0, v1);
    }
}

// ---------------- enc / dec / filter ----------------
__global__ void enc_kernel(const float* __restrict__ x, const float* __restrict__ w,
                           const float* __restrict__ bias, const float* __restrict__ pos,
                           float* __restrict__ h, f16* __restrict__ hh)
{
    int idx = blockIdx.x * 256 + threadIdx.x;
    if (idx >= NB * DIM * HW / 2) return;
    int e = idx * 2;
    int p = e & (HW - 1);
    int o = (e >> 16) & (DIM - 1);
    int b = e >> 23;
    float x0 = x[(size_t)(b * 2 + 0) * HW + p];
    float x1 = x[(size_t)(b * 2 + 1) * HW + p];
    float x0b = x[(size_t)(b * 2 + 0) * HW + p + 1];
    float x1b = x[(size_t)(b * 2 + 1) * HW + p + 1];
    float w0 = w[o * 2], w1 = w[o * 2 + 1], bb = bias[o];
    float v0 = (w0 * x0 + w1 * x1 + bb) * 8.0f + pos[(size_t)o * HW + p];
    float v1 = (w0 * x0b + w1 * x1b + bb) * 8.0f + pos[(size_t)o * HW + p + 1];
    *(float2*)(h + e) = make_float2(v0, v1);
    *(uint32_t*)(hh + e) = pack_f16x2(v0, v1);
}

__global__ void dec_kernel(const float* __restrict__ h, const float* __restrict__ w,
                           const float* __restrict__ bias, float* __restrict__ out)
{
    int idx = blockIdx.x * 256 + threadIdx.x;
    if (idx >= NB * HW) return;
    int p = idx & (HW - 1);
    int b = idx >> 16;
    const float* hb = h + (size_t)b * DIM * HW + p;
    float a0 = 0.f, a1 = 0.f;
#pragma unroll 4
    for (int c = 0; c < DIM; c++) {
        float hv = hb[(size_t)c * HW];
        a0 += w[c] * hv;
        a1 += w[DIM + c] * hv;
    }
    out[(size_t)(b * 2 + 0) * HW + p] = (a0 + bias[0]) * 0.125f;
    out[(size_t)(b * 2 + 1) * HW + p] = (a1 + bias[1]) * 0.125f;
}

__global__ void prep_filt(const float* __restrict__ mags, const float* __restrict__ phases,
                          float2* __restrict__ filt)
{
    int idx = blockIdx.x * 256 + threadIdx.x;
    if (idx >= DIM * HH * WHF) return;
    int kx = idx % WHF;
    int ky = (idx / WHF) % HH;
    int c  = idx / (WHF * HH);
    int kyp = (ky <= 128) ? ky : (256 - ky);
    float2 o = make_float2(0.f, 0.f);
    if (kx * kx + kyp * kyp <= 16384) {
        float sig = 1.0f / (1.0f + __expf(-mags[idx]));
        float s, co;
        sincosf(phases[idx], &s, &co);
        float sc = sig * (1.0f / 65536.0f);
        o = make_float2(sc * co, sc * s);
    }
    filt[(size_t)c * (WHF * 256) + (size_t)kx * 256 + drev4(ky)] = o;
}

// ---------------- launch ----------------
extern "C" void kernel_launch(void* const* d_in, const int* in_sizes, int n_in,
                              void* d_out, int out_size)
{
    const float* x      = (const float*)d_in[0];
    const float* enc_w  = (const float*)d_in[1];
    const float* enc_b  = (const float*)d_in[2];
    const float* pos    = (const float*)d_in[3];
    const float* w1     = (const float*)d_in[4];
    const float* b1     = (const float*)d_in[5];
    const float* w2     = (const float*)d_in[6];
    const float* b2     = (const float*)d_in[7];
    const float* mags   = (const float*)d_in[8];
    const float* phases = (const float*)d_in[9];
    const float* oxw    = (const float*)d_in[10];
    const float* oxb    = (const float*)d_in[11];
    const float* dw     = (const float*)d_in[12];
    const float* db     = (const float*)d_in[13];
    float* out = (float*)d_out;

    float *h, *z;
    float2 *xf, *ft;
    f16 *hh, *yh, *zh, *w1h, *w1l, *w2h, *w2l, *oxh, *oxl;
    cudaGetSymbolAddress((void**)&h,   g_h);
    cudaGetSymbolAddress((void**)&z,   g_z);
    cudaGetSymbolAddress((void**)&xf,  g_xf);
    cudaGetSymbolAddress((void**)&ft,  g_filt);
    cudaGetSymbolAddress((void**)&hh,  g_h16);
    cudaGetSymbolAddress((void**)&yh,  g_y16);
    cudaGetSymbolAddress((void**)&zh,  g_z16);
    cudaGetSymbolAddress((void**)&w1h, g_w1h);
    cudaGetSymbolAddress((void**)&w1l, g_w1l);
    cudaGetSymbolAddress((void**)&w2h, g_w2h);
    cudaGetSymbolAddress((void**)&w2l, g_w2l);
    cudaGetSymbolAddress((void**)&oxh, g_oxh);
    cudaGetSymbolAddress((void**)&oxl, g_oxl);

    const int SMEM = 3 * 32768;                      // 96 KB
    static bool attr = false;
    if (!attr) {
        cudaFuncSetAttribute(gemm_mma<128, 512, 1>, cudaFuncAttributeMaxDynamicSharedMemorySize, SMEM);
        cudaFuncSetAttribute(gemm_mma<512, 128, 0>, cudaFuncAttributeMaxDynamicSharedMemorySize, SMEM);
        cudaFuncSetAttribute(gemm_mma<128, 128, 2>, cudaFuncAttributeMaxDynamicSharedMemorySize, SMEM);
        attr = true;
    }

    wsplit<<<(NLAYERS * HID * DIM + 255) / 256, 256>>>(w1, w1h, w1l, NLAYERS * HID * DIM);
    wsplit<<<(NLAYERS * DIM * HID + 255) / 256, 256>>>(w2, w2h, w2l, NLAYERS * DIM * HID);
    wsplit<<<(NLAYERS * DIM * DIM + 255) / 256, 256>>>(oxw, oxh, oxl, NLAYERS * DIM * DIM);

    enc_kernel<<<(NB * DIM * HW / 2 + 255) / 256, 256>>>(x, enc_w, enc_b, pos, h, hh);

    const size_t specL = (size_t)DIM * HH * WHF;
    for (int i = 0; i < NLAYERS; i++) {
        prep_filt<<<(int)((specL + 255) / 256), 256>>>(mags + i * specL, phases + i * specL, ft);

        gemm_mma<128, 512, 1><<<dim3(256, 4, NB), 512, SMEM>>>(
            w1h + (size_t)i * HID * DIM, w1l + (size_t)i * HID * DIM,
            hh, b1 + i * HID, nullptr, yh);
        gemm_mma<512, 128, 0><<<dim3(256, 1, NB), 512, SMEM>>>(
            w2h + (size_t)i * DIM * HID, w2l + (size_t)i * DIM * HID,
            yh, b2 + i * DIM, z, nullptr);

        fft_row_fwd<<<dim3(NB * DIM, 16), 256>>>(z, xf);
        fft_col<<<(NB * DIM * WHF) / 16, 256>>>(xf, ft);
        fft_row_inv<<<dim3(NB * DIM, 16), 256>>>(xf, zh);

        gemm_mma<128, 128, 2><<<dim3(256, 1, NB), 512, SMEM>>>(
            oxh + (size_t)i * DIM * DIM, oxl + (size_t)i * DIM * DIM,
            zh, oxb + i * DIM, h, hh);
    }

    dec_kernel<<<(NB * HW + 255) / 256, 256>>>(h, dw, db, out);
}

// round 12
// speedup vs baseline: 1.9625x; 1.2498x over previous
#include <cuda_runtime.h>
#include <cuda_fp16.h>
#include <math.h>
#include <stdint.h>

#define HH   256
#define HW   65536
#define WHF  129
#define DIM  128
#define HID  512
#define NB   4
#define NLAYERS 4
#define FSTRIDE 272   // padded row stride (float2) for the FFT shared buffer

typedef __half f16;

// ---------------- scratch (device globals) ----------------
__device__ float  g_h[(size_t)NB * DIM * HW];          // residual [b][c][p] fp32
__device__ float  g_z[(size_t)NB * DIM * HW];          // fft input fp32
__device__ __align__(16) float2 g_xf[(size_t)NB * DIM * WHF * 256];
__device__ __align__(16) float2 g_filt[(size_t)DIM * WHF * 256];
__device__ f16    g_h16[(size_t)NB * DIM * HW];        // fp16 activations
__device__ f16    g_y16[(size_t)NB * HID * HW];
__device__ f16    g_z16[(size_t)NB * DIM * HW];
__device__ f16    g_w1h[(size_t)NLAYERS * HID * DIM], g_w1l[(size_t)NLAYERS * HID * DIM];
__device__ f16    g_w2h[(size_t)NLAYERS * DIM * HID], g_w2l[(size_t)NLAYERS * DIM * HID];
__device__ f16    g_oxh[(size_t)NLAYERS * DIM * DIM], g_oxl[(size_t)NLAYERS * DIM * DIM];

// ---------------- helpers ----------------
__device__ __forceinline__ float2 cadd(float2 a, float2 b){ return make_float2(a.x+b.x, a.y+b.y); }
__device__ __forceinline__ float2 csub(float2 a, float2 b){ return make_float2(a.x-b.x, a.y-b.y); }
__device__ __forceinline__ float2 cmul(float2 a, float2 b){
    return make_float2(a.x*b.x - a.y*b.y, a.x*b.y + a.y*b.x);
}
__device__ __forceinline__ float2 cmulc(float2 a, float2 b){   // a * conj(b)
    return make_float2(a.x*b.x + a.y*b.y, a.y*b.x - a.x*b.y);
}
__device__ __forceinline__ uint32_t smem_u32(const void* p) {
    uint32_t a;
    asm("{ .reg .u64 t; cvta.to.shared.u64 t, %1; cvt.u32.u64 %0, t; }" : "=r"(a) : "l"(p));
    return a;
}
__device__ __forceinline__ uint32_t pack_f16x2(float a, float b) {
    return ((uint32_t)__half_as_ushort(__float2half_rn(b)) << 16)
         |  (uint32_t)__half_as_ushort(__float2half_rn(a));
}

// ================= mma.sync primitives =================
__device__ __forceinline__ void ldsm4(uint32_t* r, uint32_t addr) {
    asm volatile("ldmatrix.sync.aligned.m8n8.x4.shared.b16 {%0,%1,%2,%3}, [%4];"
                 : "=r"(r[0]), "=r"(r[1]), "=r"(r[2]), "=r"(r[3]) : "r"(addr));
}
__device__ __forceinline__ void ldsm4t(uint32_t* r, uint32_t addr) {
    asm volatile("ldmatrix.sync.aligned.m8n8.x4.trans.shared.b16 {%0,%1,%2,%3}, [%4];"
                 : "=r"(r[0]), "=r"(r[1]), "=r"(r[2]), "=r"(r[3]) : "r"(addr));
}
__device__ __forceinline__ void mma16816(float* c, const uint32_t* a, const uint32_t* b) {
    asm volatile(
        "mma.sync.aligned.m16n8k16.row.col.f32.f16.f16.f32 "
        "{%0,%1,%2,%3}, {%4,%5,%6,%7}, {%8,%9}, {%0,%1,%2,%3};"
        : "+f"(c[0]), "+f"(c[1]), "+f"(c[2]), "+f"(c[3])
        : "r"(a[0]), "r"(a[1]), "r"(a[2]), "r"(a[3]), "r"(b[0]), "r"(b[1]));
}
__device__ __forceinline__ void cp16(uint32_t dst, const void* src) {
    asm volatile("cp.async.cg.shared.global [%0], [%1], 16;" :: "r"(dst), "l"(src));
}

// ================= fp16 2-pass pipelined tensor-core GEMM (R11, verified) =================
template <int K, int M, int EPI>
__global__ void __launch_bounds__(512, 1)
gemm_mma(const f16* __restrict__ Ah, const f16* __restrict__ Al,
         const f16* __restrict__ Bm,
         const float* __restrict__ bias,
         float* __restrict__ Cf, f16* __restrict__ Ch)
{
    constexpr int NC = K / 32;
    constexpr int STAGE = 32768;
    extern __shared__ uint8_t smem[];
    uint32_t sbase = smem_u32(smem);

    int tid  = threadIdx.x;
    int lane = tid & 31;
    int warp = tid >> 5;
    int wm = warp >> 2, wn = warp & 3;

    const f16* Ahp = Ah + (size_t)blockIdx.y * 128 * K;
    const f16* Alp = Al + (size_t)blockIdx.y * 128 * K;
    const f16* Bp  = Bm + (size_t)blockIdx.z * K * HW + blockIdx.x * 256;

    const f16* gp[4];
    uint32_t   off[4];
    {
        int tile = tid >> 5, line = tid & 31;
        int am  = ((tile >> 1) << 4) + (line & 15);
        int agg = ((tile & 1) << 1) + (line >> 4);
        size_t aoff = (size_t)am * K + agg * 8;
        gp[0] = Ahp + aoff;  gp[1] = Alp + aoff;
        off[0] = tile * 512 + line * 16;
        off[1] = off[0] + 8192;
        int bk  = line & 15;
        int bgn = (tile & 15) * 2 + (line >> 4);
        gp[2] = Bp + (size_t)bk * HW + bgn * 8;
        gp[3] = Bp + (size_t)(bk + 16) * HW + bgn * 8;
        off[2] = 16384 + tile * 512 + line * 16;
        off[3] = 16384 + (tile + 16) * 512 + line * 16;
    }

    auto issue = [&](int c) {
        uint32_t sst = sbase + (c % 3) * STAGE;
        cp16(sst + off[0], gp[0]);  gp[0] += 32;
        cp16(sst + off[1], gp[1]);  gp[1] += 32;
        cp16(sst + off[2], gp[2]);  gp[2] += (size_t)32 * HW;
        cp16(sst + off[3], gp[3]);  gp[3] += (size_t)32 * HW;
        asm volatile("cp.async.commit_group;" ::: "memory");
    };

    float acc[2][8][4] = {};

    issue(0);
    if (NC > 1) issue(1);

    for (int c = 0; c < NC; c++) {
        if (c + 1 < NC) {
            asm volatile("cp.async.wait_group 1;" ::: "memory");
        } else {
            asm volatile("cp.async.wait_group 0;" ::: "memory");
        }
        __syncthreads();
        uint32_t st = sbase + (c % 3) * STAGE;
#pragma unroll
        for (int kb = 0; kb < 2; kb++) {
            uint32_t ah[2][4], al[2][4];
#pragma unroll
            for (int i = 0; i < 2; i++) {
                uint32_t ad = st + ((((wm * 2 + i) * 2) + kb) << 9) + lane * 16;
                ldsm4(ah[i], ad);
                ldsm4(al[i], ad + 8192);
            }
#pragma unroll
            for (int r = 0; r < 4; r++) {
                uint32_t bh[4];
                uint32_t bd = st + 16384 + ((kb * 16 + wn * 4 + r) << 9) + lane * 16;
                ldsm4t(bh, bd);
#pragma unroll
                for (int i = 0; i < 2; i++)
#pragma unroll
                    for (int hh = 0; hh < 2; hh++) {
                        float* a_ = acc[i][r * 2 + hh];
                        mma16816(a_, ah[i], &bh[hh * 2]);
                        mma16816(a_, al[i], &bh[hh * 2]);
                    }
            }
        }
        __syncthreads();
        if (c + 2 < NC) issue(c + 2);
    }

    int g = lane >> 2;
    int mb0   = blockIdx.y * 128 + wm * 32;
    int nbase = blockIdx.x * 256 + wn * 64 + (lane & 3) * 2;
    size_t batch = (size_t)blockIdx.z * M * HW;
#pragma unroll
    for (int i = 0; i < 2; i++) {
        int r0 = mb0 + i * 16 + g;
        float bi0 = bias[r0], bi1 = bias[r0 + 8];
        size_t o0 = batch + (size_t)r0 * HW + nbase;
        size_t o1 = o0 + (size_t)8 * HW;
#pragma unroll
        for (int j = 0; j < 8; j++) {
            float v0 = acc[i][j][0] + bi0, v1 = acc[i][j][1] + bi0;
            float v2 = acc[i][j][2] + bi1, v3 = acc[i][j][3] + bi1;
            if (EPI == 1) {
                v0 = v0 / (1.f + __expf(-v0)); v1 = v1 / (1.f + __expf(-v1));
                v2 = v2 / (1.f + __expf(-v2)); v3 = v3 / (1.f + __expf(-v3));
            }
            if (EPI == 2) {
                float2 r0f = *(float2*)(Cf + o0 + j * 8);
                float2 r1f = *(float2*)(Cf + o1 + j * 8);
                v0 += r0f.x; v1 += r0f.y; v2 += r1f.x; v3 += r1f.y;
            }
            if (EPI == 0 || EPI == 2) {
                *(float2*)(Cf + o0 + j * 8) = make_float2(v0, v1);
                *(float2*)(Cf + o1 + j * 8) = make_float2(v2, v3);
            }
            if (EPI == 1 || EPI == 2) {
                *(uint32_t*)(Ch + o0 + j * 8) = pack_f16x2(v0, v1);
                *(uint32_t*)(Ch + o1 + j * 8) = pack_f16x2(v2, v3);
            }
        }
    }
}

// ---------------- weight split (fp16 hi/lo) ----------------
__global__ void wsplit(const float* __restrict__ w, f16* __restrict__ wh,
                       f16* __restrict__ wl, int n)
{
    int i = blockIdx.x * 256 + threadIdx.x;
    if (i >= n) return;
    float v = w[i];
    f16 h = __float2half_rn(v);
    wh[i] = h;
    wl[i] = __float2half_rn(v - __half2float(h));
}

// ================= four-step register FFT (256 = 16 x 16) =================
__device__ __forceinline__ float2 tw16mul(float2 v, float c, float s, bool inv) {
    float ss = inv ? -s : s;
    return make_float2(v.x * c - v.y * ss, v.x * ss + v.y * c);
}

// In-register 16-pt DFT, natural in/out. INV=false: e^{-2pi i jk/16}; INV=true: conj kernel.
template <bool INV>
__device__ __forceinline__ void dft16(float2* x) {
    float2 u[16];
#pragma unroll
    for (int j1 = 0; j1 < 4; j1++) {
        float2 a = x[j1], b = x[j1 + 4], c = x[j1 + 8], d = x[j1 + 12];
        float2 t0 = cadd(a, c), t1 = csub(a, c);
        float2 t2 = cadd(b, d), t3 = csub(b, d);
        float2 r3 = INV ? make_float2(-t3.y, t3.x) : make_float2(t3.y, -t3.x);
        u[j1 * 4 + 0] = cadd(t0, t2);
        u[j1 * 4 + 1] = cadd(t1, r3);
        u[j1 * 4 + 2] = csub(t0, t2);
        u[j1 * 4 + 3] = csub(t1, r3);
    }
    // W16^{j1*a} twiddles (forward values; INV conjugates)
    u[5]  = tw16mul(u[5],  0.92387953f, -0.38268343f, INV);
    u[6]  = tw16mul(u[6],  0.70710678f, -0.70710678f, INV);
    u[7]  = tw16mul(u[7],  0.38268343f, -0.92387953f, INV);
    u[9]  = tw16mul(u[9],  0.70710678f, -0.70710678f, INV);
    u[10] = tw16mul(u[10], 0.0f,        -1.0f,        INV);
    u[11] = tw16mul(u[11], -0.70710678f,-0.70710678f, INV);
    u[13] = tw16mul(u[13], 0.38268343f, -0.92387953f, INV);
    u[14] = tw16mul(u[14], -0.70710678f,-0.70710678f, INV);
    u[15] = tw16mul(u[15], -0.92387953f, 0.38268343f, INV);
#pragma unroll
    for (int a = 0; a < 4; a++) {
        float2 p = u[a], q = u[4 + a], r = u[8 + a], s = u[12 + a];
        float2 t0 = cadd(p, r), t1 = csub(p, r);
        float2 t2 = cadd(q, s), t3 = csub(q, s);
        float2 r3 = INV ? make_float2(-t3.y, t3.x) : make_float2(t3.y, -t3.x);
        x[a + 0]  = cadd(t0, t2);
        x[a + 4]  = cadd(t1, r3);
        x[a + 8]  = csub(t0, t2);
        x[a + 12] = csub(t1, r3);
    }
}

// tw256 init: tw[k] = exp(-2*pi*i*k/256)
#define TW256_INIT()                                                     \
    do { float s_, c_;                                                   \
        sincospif(-(float)threadIdx.x / 128.0f, &s_, &c_);               \
        tw[threadIdx.x] = make_float2(c_, s_); } while (0)

// x-row forward real FFT: z[img][y][x] natural -> xf[img][kx][y] natural, kx<129
__global__ void fft_row_fwd(const float* __restrict__ z, float2* __restrict__ xf)
{
    __shared__ float2 sb[16 * FSTRIDE];
    __shared__ float2 tw[256];
    TW256_INIT();
    int tid = threadIdx.x;
    int r = tid >> 4, q1 = tid & 15;
    int img = blockIdx.x, y0 = blockIdx.y * 16;
    const float* src = z + (size_t)img * HW + (size_t)y0 * 256;
    for (int q = tid; q < 1024; q += 256) {                 // 16 rows x 64 float4
        float4 v = ((const float4*)src)[q];
        float2* rp = &sb[(q >> 6) * FSTRIDE + (q & 63) * 4];
        rp[0] = make_float2(v.x, 0.f); rp[1] = make_float2(v.y, 0.f);
        rp[2] = make_float2(v.z, 0.f); rp[3] = make_float2(v.w, 0.f);
    }
    __syncthreads();
    float2 X[16];
#pragma unroll
    for (int n2 = 0; n2 < 16; n2++) X[n2] = sb[r * FSTRIDE + q1 + 16 * n2];
    __syncthreads();
    dft16<false>(X);                                        // over n2 -> index k1
#pragma unroll
    for (int k1 = 0; k1 < 16; k1++) X[k1] = cmul(X[k1], tw[q1 * k1]);
#pragma unroll
    for (int k1 = 0; k1 < 16; k1++) sb[r * FSTRIDE + k1 * 17 + q1] = X[k1];
    __syncthreads();
#pragma unroll
    for (int j = 0; j < 16; j++) X[j] = sb[r * FSTRIDE + q1 * 17 + j];
    dft16<false>(X);                                        // over n1 -> X[k1+16k2]
    __syncthreads();
#pragma unroll
    for (int k2 = 0; k2 < 16; k2++) sb[r * FSTRIDE + q1 + 16 * k2] = X[k2];
    __syncthreads();
    float2* dst = xf + (size_t)img * (WHF * 256) + y0;
    for (int idx = tid; idx < WHF * 16; idx += 256) {
        int kx = idx >> 4, ry = idx & 15;
        dst[(size_t)kx * 256 + ry] = sb[ry * FSTRIDE + kx];
    }
}

// y-column: fwd FFT -> filter (natural ky) -> inv FFT, in place on xf lines
__global__ void fft_col(float2* __restrict__ xf, const float2* __restrict__ filt)
{
    __shared__ float2 sb[16 * FSTRIDE];
    __shared__ float2 tw[256];
    TW256_INIT();
    int tid = threadIdx.x;
    int r = tid >> 4, q1 = tid & 15;
    size_t l0 = (size_t)blockIdx.x * 16;
    float2* src = xf + l0 * 256;
    const float4* src4 = (const float4*)src;
    for (int q = tid; q < 2048; q += 256)                   // 16 rows x 128 float4
        ((float4*)&sb[(q >> 7) * FSTRIDE])[q & 127] = src4[q];
    __syncthreads();
    float2 X[16];
#pragma unroll
    for (int n2 = 0; n2 < 16; n2++) X[n2] = sb[r * FSTRIDE + q1 + 16 * n2];
    __syncthreads();
    dft16<false>(X);
#pragma unroll
    for (int k1 = 0; k1 < 16; k1++) X[k1] = cmul(X[k1], tw[q1 * k1]);
#pragma unroll
    for (int k1 = 0; k1 < 16; k1++) sb[r * FSTRIDE + k1 * 17 + q1] = X[k1];
    __syncthreads();
#pragma unroll
    for (int j = 0; j < 16; j++) X[j] = sb[r * FSTRIDE + q1 * 17 + j];
    dft16<false>(X);                                        // X[k2] = spec at ky=q1+16k2
    {                                                       // filter, coalesced over q1
        size_t fl = ((l0 + r) % (size_t)(DIM * WHF)) * 256;
#pragma unroll
        for (int k2 = 0; k2 < 16; k2++)
            X[k2] = cmul(X[k2], filt[fl + q1 + 16 * k2]);
    }
    dft16<true>(X);                                         // IDFT over k2 -> index n1
#pragma unroll
    for (int n1 = 0; n1 < 16; n1++) X[n1] = cmulc(X[n1], tw[q1 * n1]);
    __syncthreads();
#pragma unroll
    for (int n1 = 0; n1 < 16; n1++) sb[r * FSTRIDE + n1 * 17 + q1] = X[n1];
    __syncthreads();
#pragma unroll
    for (int j = 0; j < 16; j++) X[j] = sb[r * FSTRIDE + q1 * 17 + j];
    dft16<true>(X);                                         // IDFT over k1 -> x[n1+16n2]
    __syncthreads();
#pragma unroll
    for (int n2 = 0; n2 < 16; n2++) sb[r * FSTRIDE + q1 + 16 * n2] = X[n2];
    __syncthreads();
    float4* dst4 = (float4*)src;
    for (int q = tid; q < 2048; q += 256)
        dst4[q] = ((float4*)&sb[(q >> 7) * FSTRIDE])[q & 127];
}

// x-row inverse (c2r): xf[img][kx][y] natural -> z16[img][y][x] fp16
__global__ void fft_row_inv(const float2* __restrict__ xf, f16* __restrict__ zh)
{
    __shared__ float2 sb[16 * FSTRIDE];
    __shared__ float2 tw[256];
    TW256_INIT();
    int tid = threadIdx.x;
    int r = tid >> 4, q1 = tid & 15;
    int img = blockIdx.x, y0 = blockIdx.y * 16;
    const float2* src = xf + (size_t)img * (WHF * 256) + y0;
    for (int idx = tid; idx < WHF * 16; idx += 256) {
        int kx = idx >> 4, ry = idx & 15;
        sb[ry * FSTRIDE + kx] = src[(size_t)kx * 256 + ry];
    }
    __syncthreads();
    for (int q = tid; q < 16 * 127; q += 256) {             // Hermitian fill, natural
        int rr = q / 127;
        int k = 129 + (q % 127);
        float2 v = sb[rr * FSTRIDE + 256 - k];
        sb[rr * FSTRIDE + k] = make_float2(v.x, -v.y);
    }
    __syncthreads();
    float2 X[16];
#pragma unroll
    for (int k2 = 0; k2 < 16; k2++) X[k2] = sb[r * FSTRIDE + q1 + 16 * k2];
    __syncthreads();
    dft16<true>(X);                                         // IDFT over k2 -> n1
#pragma unroll
    for (int n1 = 0; n1 < 16; n1++) X[n1] = cmulc(X[n1], tw[q1 * n1]);
#pragma unroll
    for (int n1 = 0; n1 < 16; n1++) sb[r * FSTRIDE + n1 * 17 + q1] = X[n1];
    __syncthreads();
#pragma unroll
    for (int j = 0; j < 16; j++) X[j] = sb[r * FSTRIDE + q1 * 17 + j];
    dft16<true>(X);                                         // IDFT over k1 -> x natural
    __syncthreads();
#pragma unroll
    for (int n2 = 0; n2 < 16; n2++) sb[r * FSTRIDE + q1 + 16 * n2] = X[n2];
    __syncthreads();
    size_t o = (size_t)img * HW + (size_t)y0 * 256;
    for (int idx = tid; idx < 2048; idx += 256) {
        float v0 = sb[(idx >> 7) * FSTRIDE + (idx & 127) * 2].x;
        float v1 = sb[(idx >> 7) * FSTRIDE + (idx & 127) * 2 + 1].x;
        *(uint32_t*)(zh + o + idx * 2) = pack_f16x2(v0, v1);
    }
}

// ---------------- enc / dec / filter ----------------
__global__ void enc_kernel(const float* __restrict__ x, const float* __restrict__ w,
                           const float* __restrict__ bias, const float* __restrict__ pos,
                           float* __restrict__ h, f16* __restrict__ hh)
{
    int idx = blockIdx.x * 256 + threadIdx.x;
    if (idx >= NB * DIM * HW / 2) return;
    int e = idx * 2;
    int p = e & (HW - 1);
    int o = (e >> 16) & (DIM - 1);
    int b = e >> 23;
    float x0 = x[(size_t)(b * 2 + 0) * HW + p];
    float x1 = x[(size_t)(b * 2 + 1) * HW + p];
    float x0b = x[(size_t)(b * 2 + 0) * HW + p + 1];
    float x1b = x[(size_t)(b * 2 + 1) * HW + p + 1];
    float w0 = w[o * 2], w1 = w[o * 2 + 1], bb = bias[o];
    float v0 = (w0 * x0 + w1 * x1 + bb) * 8.0f + pos[(size_t)o * HW + p];
    float v1 = (w0 * x0b + w1 * x1b + bb) * 8.0f + pos[(size_t)o * HW + p + 1];
    *(float2*)(h + e) = make_float2(v0, v1);
    *(uint32_t*)(hh + e) = pack_f16x2(v0, v1);
}

__global__ void dec_kernel(const float* __restrict__ h, const float* __restrict__ w,
                           const float* __restrict__ bias, float* __restrict__ out)
{
    int idx = blockIdx.x * 256 + threadIdx.x;
    if (idx >= NB * HW) return;
    int p = idx & (HW - 1);
    int b = idx >> 16;
    const float* hb = h + (size_t)b * DIM * HW + p;
    float a0 = 0.f, a1 = 0.f;
#pragma unroll 4
    for (int c = 0; c < DIM; c++) {
        float hv = hb[(size_t)c * HW];
        a0 += w[c] * hv;
        a1 += w[DIM + c] * hv;
    }
    out[(size_t)(b * 2 + 0) * HW + p] = (a0 + bias[0]) * 0.125f;
    out[(size_t)(b * 2 + 1) * HW + p] = (a1 + bias[1]) * 0.125f;
}

__global__ void prep_filt(const float* __restrict__ mags, const float* __restrict__ phases,
                          float2* __restrict__ filt)
{
    int idx = blockIdx.x * 256 + threadIdx.x;
    if (idx >= DIM * HH * WHF) return;
    int kx = idx % WHF;
    int ky = (idx / WHF) % HH;
    int c  = idx / (WHF * HH);
    int kyp = (ky <= 128) ? ky : (256 - ky);
    float2 o = make_float2(0.f, 0.f);
    if (kx * kx + kyp * kyp <= 16384) {
        float sig = 1.0f / (1.0f + __expf(-mags[idx]));
        float s, co;
        sincosf(phases[idx], &s, &co);
        float sc = sig * (1.0f / 65536.0f);
        o = make_float2(sc * co, sc * s);
    }
    filt[(size_t)c * (WHF * 256) + (size_t)kx * 256 + ky] = o;   // natural ky
}

// ---------------- launch ----------------
extern "C" void kernel_launch(void* const* d_in, const int* in_sizes, int n_in,
                              void* d_out, int out_size)
{
    const float* x      = (const float*)d_in[0];
    const float* enc_w  = (const float*)d_in[1];
    const float* enc_b  = (const float*)d_in[2];
    const float* pos    = (const float*)d_in[3];
    const float* w1     = (const float*)d_in[4];
    const float* b1     = (const float*)d_in[5];
    const float* w2     = (const float*)d_in[6];
    const float* b2     = (const float*)d_in[7];
    const float* mags   = (const float*)d_in[8];
    const float* phases = (const float*)d_in[9];
    const float* oxw    = (const float*)d_in[10];
    const float* oxb    = (const float*)d_in[11];
    const float* dw     = (const float*)d_in[12];
    const float* db     = (const float*)d_in[13];
    float* out = (float*)d_out;

    float *h, *z;
    float2 *xf, *ft;
    f16 *hh, *yh, *zh, *w1h, *w1l, *w2h, *w2l, *oxh, *oxl;
    cudaGetSymbolAddress((void**)&h,   g_h);
    cudaGetSymbolAddress((void**)&z,   g_z);
    cudaGetSymbolAddress((void**)&xf,  g_xf);
    cudaGetSymbolAddress((void**)&ft,  g_filt);
    cudaGetSymbolAddress((void**)&hh,  g_h16);
    cudaGetSymbolAddress((void**)&yh,  g_y16);
    cudaGetSymbolAddress((void**)&zh,  g_z16);
    cudaGetSymbolAddress((void**)&w1h, g_w1h);
    cudaGetSymbolAddress((void**)&w1l, g_w1l);
    cudaGetSymbolAddress((void**)&w2h, g_w2h);
    cudaGetSymbolAddress((void**)&w2l, g_w2l);
    cudaGetSymbolAddress((void**)&oxh, g_oxh);
    cudaGetSymbolAddress((void**)&oxl, g_oxl);

    const int SMEM = 3 * 32768;                      // 96 KB
    static bool attr = false;
    if (!attr) {
        cudaFuncSetAttribute(gemm_mma<128, 512, 1>, cudaFuncAttributeMaxDynamicSharedMemorySize, SMEM);
        cudaFuncSetAttribute(gemm_mma<512, 128, 0>, cudaFuncAttributeMaxDynamicSharedMemorySize, SMEM);
        cudaFuncSetAttribute(gemm_mma<128, 128, 2>, cudaFuncAttributeMaxDynamicSharedMemorySize, SMEM);
        attr = true;
    }

    wsplit<<<(NLAYERS * HID * DIM + 255) / 256, 256>>>(w1, w1h, w1l, NLAYERS * HID * DIM);
    wsplit<<<(NLAYERS * DIM * HID + 255) / 256, 256>>>(w2, w2h, w2l, NLAYERS * DIM * HID);
    wsplit<<<(NLAYERS * DIM * DIM + 255) / 256, 256>>>(oxw, oxh, oxl, NLAYERS * DIM * DIM);

    enc_kernel<<<(NB * DIM * HW / 2 + 255) / 256, 256>>>(x, enc_w, enc_b, pos, h, hh);

    const size_t specL = (size_t)DIM * HH * WHF;
    for (int i = 0; i < NLAYERS; i++) {
        prep_filt<<<(int)((specL + 255) / 256), 256>>>(mags + i * specL, phases + i * specL, ft);

        gemm_mma<128, 512, 1><<<dim3(256, 4, NB), 512, SMEM>>>(
            w1h + (size_t)i * HID * DIM, w1l + (size_t)i * HID * DIM,
            hh, b1 + i * HID, nullptr, yh);
        gemm_mma<512, 128, 0><<<dim3(256, 1, NB), 512, SMEM>>>(
            w2h + (size_t)i * DIM * HID, w2l + (size_t)i * DIM * HID,
            yh, b2 + i * DIM, z, nullptr);

        fft_row_fwd<<<dim3(NB * DIM, 16), 256>>>(z, xf);
        fft_col<<<(NB * DIM * WHF) / 16, 256>>>(xf, ft);
        fft_row_inv<<<dim3(NB * DIM, 16), 256>>>(xf, zh);

        gemm_mma<128, 128, 2><<<dim3(256, 1, NB), 512, SMEM>>>(
            oxh + (size_t)i * DIM * DIM, oxl + (size_t)i * DIM * DIM,
            zh, oxb + i * DIM, h, hh);
    }

    dec_kernel<<<(NB * HW + 255) / 256, 256>>>(h, dw, db, out);
}